// round 5
// baseline (speedup 1.0000x reference)
#include <cuda_runtime.h>
#include <cuda_bf16.h>
#include <cstdint>

#define DD 128
#define TM 128
#define TK 64
#define NTHREADS 256

// ---- device scratch (no allocations allowed) ----
__device__ double g_acc;
__device__ unsigned int g_done;
__device__ float g_a[4096];                    // ||sub_x_i||^2
__device__ float g_b[8192];                    // ||all_x_j||^2
__device__ __align__(16) __nv_bfloat16 g_Yt[128 * 8192];  // all_x^T bf16: [d][n]

// ---- dynamic smem layout (bytes) ----
#define Y_STAGE 16384                  // 128 rows * 128B, XOR-swizzled
#define G_SIZE  16384
#define SM_Y 0                         // 3 stages
#define SM_G (3 * Y_STAGE)             // 2 buffers
#define SM_WSUM (SM_G + 2 * G_SIZE)
#define SMEM_TOTAL (SM_WSUM + 64)

// ---------------------------------------------------------------------------
static __device__ __forceinline__ uint32_t smem_u32(const void* p) {
    return (uint32_t)__cvta_generic_to_shared(p);
}
static __device__ __forceinline__ void cpa16(uint32_t smem_dst, const void* gsrc) {
    asm volatile("cp.async.cg.shared.global [%0], [%1], 16;\n" ::"r"(smem_dst), "l"(gsrc));
}
static __device__ __forceinline__ void cpa_commit() {
    asm volatile("cp.async.commit_group;\n" ::: "memory");
}
static __device__ __forceinline__ void ldsm_x4(uint32_t* r, uint32_t addr) {
    asm volatile("ldmatrix.sync.aligned.m8n8.x4.shared.b16 {%0,%1,%2,%3}, [%4];"
                 : "=r"(r[0]), "=r"(r[1]), "=r"(r[2]), "=r"(r[3]) : "r"(addr));
}

// ---------------------------------------------------------------------------
// prep: per-row sumsq for sub_x (-> g_a) and all_x (-> g_b), plus bf16
// transposed copy of all_x into g_Yt[d][n]. One block = 32 rows.
// Also zeros g_acc / g_done.
// ---------------------------------------------------------------------------
__global__ void prep_kernel(const float* __restrict__ subx,
                            const float* __restrict__ allx, int m, int n) {
    __shared__ float ys[32 * 132];
    int b = blockIdx.x;
    int t = threadIdx.x;
    if (b == 0 && t == 0) { g_acc = 0.0; g_done = 0u; }
    int nb_y = n / 32;
    bool isY = b < nb_y;
    const float* src = isY ? allx : subx;
    int r0 = isY ? b * 32 : (b - nb_y) * 32;

#pragma unroll
    for (int i = 0; i < 4; i++) {
        int ci = i * 256 + t;
        int rl = ci >> 5, c4 = ci & 31;
        float4 v = *(const float4*)(src + (size_t)(r0 + rl) * DD + c4 * 4);
        *(float4*)(ys + rl * 132 + c4 * 4) = v;
    }
    __syncthreads();

    {
        int rl = t >> 3, sub = t & 7;
        const float* row = ys + rl * 132 + sub * 16;
        float s = 0.f;
#pragma unroll
        for (int i = 0; i < 16; i++) { float v = row[i]; s += v * v; }
        s += __shfl_down_sync(0xffffffffu, s, 4, 8);
        s += __shfl_down_sync(0xffffffffu, s, 2, 8);
        s += __shfl_down_sync(0xffffffffu, s, 1, 8);
        if (sub == 0) { if (isY) g_b[r0 + rl] = s; else g_a[r0 + rl] = s; }
    }

    if (isY) {
        int d = t >> 1, half = t & 1;
        uint32_t pk[8];
#pragma unroll
        for (int i = 0; i < 8; i++) {
            int r = half * 16 + i * 2;
            float f0 = ys[r * 132 + d];
            float f1 = ys[(r + 1) * 132 + d];
            __nv_bfloat162 h = __float22bfloat162_rn(make_float2(f0, f1));
            pk[i] = *(uint32_t*)&h;
        }
        uint4* dst = (uint4*)(g_Yt + (size_t)d * n + r0 + half * 16);
        dst[0] = make_uint4(pk[0], pk[1], pk[2], pk[3]);
        dst[1] = make_uint4(pk[4], pk[5], pk[6], pk[7]);
    }
}

// ---------------------------------------------------------------------------
// main fused kernel. 148 CTAs over 32 mtiles x k-ranges. Warp w = (qm, qn):
// 64m x 32n output block, full k per tile. acc = 64 regs/thread (no spills).
// ---------------------------------------------------------------------------
__global__ __launch_bounds__(NTHREADS, 1)
void main_kernel(const float* __restrict__ G, const float* __restrict__ X,
                 float* __restrict__ out, int m, int n) {
    extern __shared__ char smem[];
    const uint32_t sb = smem_u32(smem);
    float* wsum = (float*)(smem + SM_WSUM);

    const int t = threadIdx.x;
    const int wid = t >> 5, lane = t & 31;
    const int g = lane >> 2, tg = lane & 3;
    const int qm = wid & 1, qn = wid >> 1;   // qm: m-half, qn: n-quarter

    // ---- work split: 148 CTAs over 32 mtiles x 128 ktiles ----
    int mt, kstart, TILES;
    if (blockIdx.x < 100) {                 // 20 mtiles x 5 ranges (26,26,26,25,25)
        mt = blockIdx.x / 5;
        int r = blockIdx.x % 5;
        kstart = r * 26 - (r > 3 ? 1 : 0);
        TILES = (r < 3) ? 26 : 25;
    } else {                                // 12 mtiles x 4 ranges of 32
        int b2 = blockIdx.x - 100;
        mt = 20 + (b2 >> 2);
        kstart = (b2 & 3) * 32;
        TILES = 32;
    }
    const int m0 = mt * TM;
    const int k0 = kstart * TK;

    const int rb = t >> 3, ch = t & 7;
    float a_reg[4];
#pragma unroll
    for (int rr = 0; rr < 4; rr++) a_reg[rr] = g_a[m0 + rb + 32 * rr];

    float acc[4][4][4];                      // [ms 16-rows][ns 8-cols][frag]
#pragma unroll
    for (int i = 0; i < 4; i++)
#pragma unroll
        for (int j = 0; j < 4; j++)
#pragma unroll
            for (int c = 0; c < 4; c++) acc[i][j][c] = 0.f;
    float s_deg = 0.f;

    // ---- Y tile issue (bf16, 128 rows x 128B, XOR-swizzled) ----
    auto issue_y = [&](int stage, int tile) {
        int kk = k0 + tile * TK;
        uint32_t yv = sb + SM_Y + stage * Y_STAGE;
#pragma unroll
        for (int i = 0; i < 4; i++) {
            int ci = i * NTHREADS + t;
            int r = ci >> 3, c = ci & 7;
            cpa16(yv + r * 128 + ((c ^ (r & 7)) << 4),
                  g_Yt + (size_t)r * n + kk + c * 8);
        }
    };

    // ---- G fp32 tile + g_b in registers (one tile ahead) ----
    float4 gv[8];
    auto ldg_g = [&](int tile) {
        int kk = k0 + tile * TK;
#pragma unroll
        for (int rr = 0; rr < 4; rr++) {
            const float* p = G + (size_t)(m0 + rb + 32 * rr) * n + kk + ch * 8;
            gv[2 * rr] = *(const float4*)p;
            gv[2 * rr + 1] = *(const float4*)(p + 4);
        }
    };
    float4 bA, bB, nbA, nbB;
    auto ldg_b = [&](int tile, float4& oA, float4& oB) {
        int kk = k0 + tile * TK;
        oA = *(const float4*)(g_b + kk + ch * 8);
        oB = *(const float4*)(g_b + kk + ch * 8 + 4);
    };

    ldg_g(0);
    ldg_b(0, bA, bB);
    issue_y(0, 0); cpa_commit();
    issue_y(1, 1); cpa_commit();

    for (int tile = 0; tile < TILES; tile++) {
        uint32_t gbuf = sb + SM_G + (tile & 1) * G_SIZE;
        uint32_t ybuf = sb + SM_Y + (tile % 3) * Y_STAGE;

        // ---- G pass: exact fp32 deg terms + bf16 convert + STS ----
#pragma unroll
        for (int rr = 0; rr < 4; rr++) {
            float4 v0 = gv[2 * rr], v1 = gv[2 * rr + 1];
            float sg = v0.x + v0.y + v0.z + v0.w + v1.x + v1.y + v1.z + v1.w;
            float db = v0.x * bA.x + v0.y * bA.y + v0.z * bA.z + v0.w * bA.w +
                       v1.x * bB.x + v1.y * bB.y + v1.z * bB.z + v1.w * bB.w;
            s_deg += a_reg[rr] * sg + db;
            __nv_bfloat162 h0 = __float22bfloat162_rn(make_float2(v0.x, v0.y));
            __nv_bfloat162 h1 = __float22bfloat162_rn(make_float2(v0.z, v0.w));
            __nv_bfloat162 h2 = __float22bfloat162_rn(make_float2(v1.x, v1.y));
            __nv_bfloat162 h3 = __float22bfloat162_rn(make_float2(v1.z, v1.w));
            int r = rb + 32 * rr;
            uint32_t ad = gbuf + r * 128 + ((ch ^ (r & 7)) << 4);
            asm volatile("st.shared.v4.b32 [%0], {%1,%2,%3,%4};" ::"r"(ad),
                         "r"(*(uint32_t*)&h0), "r"(*(uint32_t*)&h1),
                         "r"(*(uint32_t*)&h2), "r"(*(uint32_t*)&h3));
        }

        if (tile + 1 < TILES) { ldg_g(tile + 1); ldg_b(tile + 1, nbA, nbB); }

        asm volatile("cp.async.wait_group 1;\n" ::: "memory");
        __syncthreads();

        if (tile + 2 < TILES) issue_y((tile + 2) % 3, tile + 2);
        cpa_commit();

        // ---- MMA: acc += G[qm-half] * Y^T[qn-quarter], full k=64 ----
#pragma unroll
        for (int ksb = 0; ksb < 4; ksb++) {
            int cb = ksb * 2;
            uint32_t A[4][4];
#pragma unroll
            for (int ms = 0; ms < 4; ms++) {
                int r = qm * 64 + ms * 16 + (lane & 15);
                int c = cb + (lane >> 4);
                ldsm_x4(A[ms], gbuf + r * 128 + ((c ^ (r & 7)) << 4));
            }
            uint32_t B[4][2];
#pragma unroll
            for (int p = 0; p < 2; p++) {
                int r = qn * 32 + p * 16 + (lane & 7) + ((lane >> 4) << 3);
                int c = cb + ((lane >> 3) & 1);
                uint32_t mm[4];
                ldsm_x4(mm, ybuf + r * 128 + ((c ^ (r & 7)) << 4));
                B[2 * p][0] = mm[0]; B[2 * p][1] = mm[1];
                B[2 * p + 1][0] = mm[2]; B[2 * p + 1][1] = mm[3];
            }
#pragma unroll
            for (int ms = 0; ms < 4; ms++)
#pragma unroll
                for (int ns = 0; ns < 4; ns++) {
                    asm volatile(
                        "mma.sync.aligned.m16n8k16.row.col.f32.bf16.bf16.f32 "
                        "{%0,%1,%2,%3},{%4,%5,%6,%7},{%8,%9},{%0,%1,%2,%3};\n"
                        : "+f"(acc[ms][ns][0]), "+f"(acc[ms][ns][1]),
                          "+f"(acc[ms][ns][2]), "+f"(acc[ms][ns][3])
                        : "r"(A[ms][0]), "r"(A[ms][1]), "r"(A[ms][2]), "r"(A[ms][3]),
                          "r"(B[ns][0]), "r"(B[ns][1]));
                }
        }
        bA = nbA; bB = nbB;
    }

    // ---- epilogue: cross partial = sum Z .* sub_x ----
    float s_cross = 0.f;
#pragma unroll
    for (int ms = 0; ms < 4; ms++) {
        int r1 = m0 + qm * 64 + ms * 16 + g;
#pragma unroll
        for (int ns = 0; ns < 4; ns++) {
            int col = qn * 32 + ns * 8 + 2 * tg;
            float2 x0 = *(const float2*)(X + (size_t)r1 * DD + col);
            float2 x1 = *(const float2*)(X + (size_t)(r1 + 8) * DD + col);
            s_cross += acc[ms][ns][0] * x0.x + acc[ms][ns][1] * x0.y +
                       acc[ms][ns][2] * x1.x + acc[ms][ns][3] * x1.y;
        }
    }

    float tot = s_deg - 2.f * s_cross;
#pragma unroll
    for (int o = 16; o > 0; o >>= 1) tot += __shfl_down_sync(0xffffffffu, tot, o);
    if (lane == 0) wsum[wid] = tot;
    __syncthreads();
    if (t == 0) {
        float s = 0.f;
#pragma unroll
        for (int i = 0; i < 8; i++) s += wsum[i];
        atomicAdd(&g_acc, (double)s);
        __threadfence();
        unsigned prev = atomicAdd(&g_done, 1u);
        if (prev == gridDim.x - 1) {          // last CTA finalizes
            g_done = 0u;
            double v = atomicAdd(&g_acc, 0.0);
            out[0] = (float)(v / (double)((long long)m * (long long)n));
        }
    }
}

extern "C" void kernel_launch(void* const* d_in, const int* in_sizes, int n_in,
                              void* d_out, int out_size) {
    const float* G = (const float*)d_in[0];   // sub_graph [m,n]
    const float* X = (const float*)d_in[1];   // sub_x [m,128]
    const float* Y = (const float*)d_in[2];   // all_x [n,128]
    int m = in_sizes[1] / DD;
    int n = in_sizes[2] / DD;

    cudaFuncSetAttribute(main_kernel, cudaFuncAttributeMaxDynamicSharedMemorySize,
                         SMEM_TOTAL);

    prep_kernel<<<(m + n) / 32, 256>>>(X, Y, m, n);
    main_kernel<<<148, NTHREADS, SMEM_TOTAL>>>(G, X, (float*)d_out, m, n);
}

// round 6
// speedup vs baseline: 1.5393x; 1.5393x over previous
#include <cuda_runtime.h>
#include <cuda_bf16.h>
#include <cstdint>

#define DD 128
#define TM 128
#define TK 64
#define NTHREADS 256
#define GRID 148

// ---- device scratch (no allocations allowed) ----
__device__ double g_acc;
__device__ unsigned int g_done;
__device__ float g_a[4096];                    // ||sub_x_i||^2
__device__ float g_b[8192];                    // ||all_x_j||^2
__device__ __align__(16) __nv_bfloat16 g_Yt[128 * 8192];  // all_x^T bf16: [d][n]

// ---- dynamic smem layout (bytes) ----
#define Y_STAGE 16384                  // 128 rows * 128B, XOR-swizzled
#define G_SIZE  16384
#define SM_Y 0                         // 3 stages
#define SM_G (3 * Y_STAGE)             // 2 buffers
#define SM_WSUM (SM_G + 2 * G_SIZE)
#define SMEM_TOTAL (SM_WSUM + 64)

// ---------------------------------------------------------------------------
static __device__ __forceinline__ uint32_t smem_u32(const void* p) {
    return (uint32_t)__cvta_generic_to_shared(p);
}
static __device__ __forceinline__ void cpa16(uint32_t smem_dst, const void* gsrc) {
    asm volatile("cp.async.cg.shared.global [%0], [%1], 16;\n" ::"r"(smem_dst), "l"(gsrc));
}
static __device__ __forceinline__ void cpa_commit() {
    asm volatile("cp.async.commit_group;\n" ::: "memory");
}
static __device__ __forceinline__ void ldsm_x4(uint32_t* r, uint32_t addr) {
    asm volatile("ldmatrix.sync.aligned.m8n8.x4.shared.b16 {%0,%1,%2,%3}, [%4];"
                 : "=r"(r[0]), "=r"(r[1]), "=r"(r[2]), "=r"(r[3]) : "r"(addr));
}

// ---------------------------------------------------------------------------
// prep: per-row sumsq for sub_x (-> g_a) and all_x (-> g_b), plus bf16
// transposed copy of all_x into g_Yt[d][n]. One block = 32 rows.
// Also zeros g_acc / g_done.
// ---------------------------------------------------------------------------
__global__ void prep_kernel(const float* __restrict__ subx,
                            const float* __restrict__ allx, int m, int n) {
    __shared__ float ys[32 * 132];
    int b = blockIdx.x;
    int t = threadIdx.x;
    if (b == 0 && t == 0) { g_acc = 0.0; g_done = 0u; }
    int nb_y = n / 32;
    bool isY = b < nb_y;
    const float* src = isY ? allx : subx;
    int r0 = isY ? b * 32 : (b - nb_y) * 32;

#pragma unroll
    for (int i = 0; i < 4; i++) {
        int ci = i * 256 + t;
        int rl = ci >> 5, c4 = ci & 31;
        float4 v = *(const float4*)(src + (size_t)(r0 + rl) * DD + c4 * 4);
        *(float4*)(ys + rl * 132 + c4 * 4) = v;
    }
    __syncthreads();

    {
        int rl = t >> 3, sub = t & 7;
        const float* row = ys + rl * 132 + sub * 16;
        float s = 0.f;
#pragma unroll
        for (int i = 0; i < 16; i++) { float v = row[i]; s += v * v; }
        s += __shfl_down_sync(0xffffffffu, s, 4, 8);
        s += __shfl_down_sync(0xffffffffu, s, 2, 8);
        s += __shfl_down_sync(0xffffffffu, s, 1, 8);
        if (sub == 0) { if (isY) g_b[r0 + rl] = s; else g_a[r0 + rl] = s; }
    }

    if (isY) {
        int d = t >> 1, half = t & 1;
        uint32_t pk[8];
#pragma unroll
        for (int i = 0; i < 8; i++) {
            int r = half * 16 + i * 2;
            float f0 = ys[r * 132 + d];
            float f1 = ys[(r + 1) * 132 + d];
            __nv_bfloat162 h = __float22bfloat162_rn(make_float2(f0, f1));
            pk[i] = *(uint32_t*)&h;
        }
        uint4* dst = (uint4*)(g_Yt + (size_t)d * n + r0 + half * 16);
        dst[0] = make_uint4(pk[0], pk[1], pk[2], pk[3]);
        dst[1] = make_uint4(pk[4], pk[5], pk[6], pk[7]);
    }
}

// ---------------------------------------------------------------------------
// main fused kernel. Work = flattened units u = mtile*KT + ktile; each of 148
// CTAs takes a contiguous 27/28-unit range, flushing acc at mtile boundaries.
// Warp w = (qm, qn, kh): 64x64 output block, k-half of each 64-wide tile.
// ---------------------------------------------------------------------------
__global__ __launch_bounds__(NTHREADS, 1)
void main_kernel(const float* __restrict__ G, const float* __restrict__ X,
                 float* __restrict__ out, int m, int n) {
    extern __shared__ char smem[];
    const uint32_t sb = smem_u32(smem);
    float* wsum = (float*)(smem + SM_WSUM);

    const int t = threadIdx.x;
    const int wid = t >> 5, lane = t & 31;
    const int g = lane >> 2, tg = lane & 3;
    const int qm = wid & 1, qn = (wid >> 1) & 1, kh = wid >> 2;
    const int kbase = kh * 32;
    const int rb = t >> 3, ch = t & 7;

    const int KT = n / TK;                       // 128
    const int U = (m / TM) * KT;                 // 4096
    const int base = U / GRID, rem = U - base * GRID;   // 27, 100
    const int bid = blockIdx.x;
    const int u0 = (bid < rem) ? bid * (base + 1)
                               : rem * (base + 1) + (bid - rem) * base;
    const int u1 = u0 + ((bid < rem) ? base + 1 : base);

    int cur_mt = u0 >> 7;                        // KT = 128 -> shift 7
    int m0 = cur_mt * TM;

    float a_reg[4];
#pragma unroll
    for (int rr = 0; rr < 4; rr++) a_reg[rr] = g_a[m0 + rb + 32 * rr];

    float acc[4][8][4];
#pragma unroll
    for (int i = 0; i < 4; i++)
#pragma unroll
        for (int j = 0; j < 8; j++)
#pragma unroll
            for (int c = 0; c < 4; c++) acc[i][j][c] = 0.f;
    float s_deg = 0.f, s_cross = 0.f;

    // ---- flush: dot acc with sub_x rows of current mtile, reset acc ----
    auto flush = [&]() {
#pragma unroll
        for (int ms = 0; ms < 4; ms++) {
            int r1 = m0 + qm * 64 + ms * 16 + g;
#pragma unroll
            for (int ns = 0; ns < 8; ns++) {
                int col = qn * 64 + ns * 8 + 2 * tg;
                float2 x0 = *(const float2*)(X + (size_t)r1 * DD + col);
                float2 x1 = *(const float2*)(X + (size_t)(r1 + 8) * DD + col);
                s_cross += acc[ms][ns][0] * x0.x + acc[ms][ns][1] * x0.y +
                           acc[ms][ns][2] * x1.x + acc[ms][ns][3] * x1.y;
                acc[ms][ns][0] = 0.f; acc[ms][ns][1] = 0.f;
                acc[ms][ns][2] = 0.f; acc[ms][ns][3] = 0.f;
            }
        }
    };

    // ---- Y tile issue for unit u (address depends only on ktile) ----
    auto issue_y = [&](int stage, int u) {
        int kk = (u & 127) * TK;
        uint32_t yv = sb + SM_Y + stage * Y_STAGE;
#pragma unroll
        for (int i = 0; i < 4; i++) {
            int ci = i * NTHREADS + t;
            int r = ci >> 3, c = ci & 7;
            cpa16(yv + r * 128 + ((c ^ (r & 7)) << 4),
                  g_Yt + (size_t)r * n + kk + c * 8);
        }
    };

    // ---- G fp32 tile + g_b in registers (one unit ahead) ----
    float4 gv[8];
    auto ldg_g = [&](int u) {
        int mm0 = (u >> 7) * TM;
        int kk = (u & 127) * TK;
#pragma unroll
        for (int rr = 0; rr < 4; rr++) {
            const float* p = G + (size_t)(mm0 + rb + 32 * rr) * n + kk + ch * 8;
            gv[2 * rr] = *(const float4*)p;
            gv[2 * rr + 1] = *(const float4*)(p + 4);
        }
    };
    float4 bA, bB, nbA, nbB;
    auto ldg_b = [&](int u, float4& oA, float4& oB) {
        int kk = (u & 127) * TK;
        oA = *(const float4*)(g_b + kk + ch * 8);
        oB = *(const float4*)(g_b + kk + ch * 8 + 4);
    };

    ldg_g(u0);
    ldg_b(u0, bA, bB);
    issue_y(0, u0); cpa_commit();
    if (u0 + 1 < u1) issue_y(1, u0 + 1);
    cpa_commit();

    for (int u = u0; u < u1; u++) {
        int it = u - u0;
        uint32_t gbuf = sb + SM_G + (it & 1) * G_SIZE;
        uint32_t ybuf = sb + SM_Y + (it % 3) * Y_STAGE;

        int mtu = u >> 7;
        if (mtu != cur_mt) {                     // mtile boundary (<=1 per CTA)
            flush();
            cur_mt = mtu;
            m0 = cur_mt * TM;
#pragma unroll
            for (int rr = 0; rr < 4; rr++) a_reg[rr] = g_a[m0 + rb + 32 * rr];
        }

        // ---- G pass: exact fp32 deg terms + bf16 convert + STS ----
#pragma unroll
        for (int rr = 0; rr < 4; rr++) {
            float4 v0 = gv[2 * rr], v1 = gv[2 * rr + 1];
            float sg = v0.x + v0.y + v0.z + v0.w + v1.x + v1.y + v1.z + v1.w;
            float db = v0.x * bA.x + v0.y * bA.y + v0.z * bA.z + v0.w * bA.w +
                       v1.x * bB.x + v1.y * bB.y + v1.z * bB.z + v1.w * bB.w;
            s_deg += a_reg[rr] * sg + db;
            __nv_bfloat162 h0 = __float22bfloat162_rn(make_float2(v0.x, v0.y));
            __nv_bfloat162 h1 = __float22bfloat162_rn(make_float2(v0.z, v0.w));
            __nv_bfloat162 h2 = __float22bfloat162_rn(make_float2(v1.x, v1.y));
            __nv_bfloat162 h3 = __float22bfloat162_rn(make_float2(v1.z, v1.w));
            int r = rb + 32 * rr;
            uint32_t ad = gbuf + r * 128 + ((ch ^ (r & 7)) << 4);
            asm volatile("st.shared.v4.b32 [%0], {%1,%2,%3,%4};" ::"r"(ad),
                         "r"(*(uint32_t*)&h0), "r"(*(uint32_t*)&h1),
                         "r"(*(uint32_t*)&h2), "r"(*(uint32_t*)&h3));
        }

        if (u + 1 < u1) { ldg_g(u + 1); ldg_b(u + 1, nbA, nbB); }

        asm volatile("cp.async.wait_group 1;\n" ::: "memory");
        __syncthreads();

        if (u + 2 < u1) issue_y((it + 2) % 3, u + 2);
        cpa_commit();

        // ---- MMA: acc += G[qm-half, k-half] * Y^T[qn-half] ----
#pragma unroll
        for (int ksb = 0; ksb < 2; ksb++) {
            int kk16 = kbase + ksb * 16;
            int cb = kk16 >> 3;
            uint32_t A[4][4];
#pragma unroll
            for (int ms = 0; ms < 4; ms++) {
                int r = qm * 64 + ms * 16 + (lane & 15);
                int c = cb + (lane >> 4);
                ldsm_x4(A[ms], gbuf + r * 128 + ((c ^ (r & 7)) << 4));
            }
            uint32_t B[8][2];
#pragma unroll
            for (int p = 0; p < 4; p++) {
                int r = qn * 64 + p * 16 + (lane & 7) + ((lane >> 4) << 3);
                int c = cb + ((lane >> 3) & 1);
                uint32_t mm[4];
                ldsm_x4(mm, ybuf + r * 128 + ((c ^ (r & 7)) << 4));
                B[2 * p][0] = mm[0]; B[2 * p][1] = mm[1];
                B[2 * p + 1][0] = mm[2]; B[2 * p + 1][1] = mm[3];
            }
#pragma unroll
            for (int ms = 0; ms < 4; ms++)
#pragma unroll
                for (int ns = 0; ns < 8; ns++) {
                    asm volatile(
                        "mma.sync.aligned.m16n8k16.row.col.f32.bf16.bf16.f32 "
                        "{%0,%1,%2,%3},{%4,%5,%6,%7},{%8,%9},{%0,%1,%2,%3};\n"
                        : "+f"(acc[ms][ns][0]), "+f"(acc[ms][ns][1]),
                          "+f"(acc[ms][ns][2]), "+f"(acc[ms][ns][3])
                        : "r"(A[ms][0]), "r"(A[ms][1]), "r"(A[ms][2]), "r"(A[ms][3]),
                          "r"(B[ns][0]), "r"(B[ns][1]));
                }
        }
        bA = nbA; bB = nbB;
    }

    // ---- final flush + reduce + fused finalize ----
    flush();
    float tot = s_deg - 2.f * s_cross;
#pragma unroll
    for (int o = 16; o > 0; o >>= 1) tot += __shfl_down_sync(0xffffffffu, tot, o);
    if (lane == 0) wsum[wid] = tot;
    __syncthreads();
    if (t == 0) {
        float s = 0.f;
#pragma unroll
        for (int i = 0; i < 8; i++) s += wsum[i];
        atomicAdd(&g_acc, (double)s);
        __threadfence();
        unsigned prev = atomicAdd(&g_done, 1u);
        if (prev == gridDim.x - 1) {
            g_done = 0u;
            double v = atomicAdd(&g_acc, 0.0);
            out[0] = (float)(v / (double)((long long)m * (long long)n));
        }
    }
}

extern "C" void kernel_launch(void* const* d_in, const int* in_sizes, int n_in,
                              void* d_out, int out_size) {
    const float* G = (const float*)d_in[0];   // sub_graph [m,n]
    const float* X = (const float*)d_in[1];   // sub_x [m,128]
    const float* Y = (const float*)d_in[2];   // all_x [n,128]
    int m = in_sizes[1] / DD;
    int n = in_sizes[2] / DD;

    cudaFuncSetAttribute(main_kernel, cudaFuncAttributeMaxDynamicSharedMemorySize,
                         SMEM_TOTAL);

    prep_kernel<<<(m + n) / 32, 256>>>(X, Y, m, n);
    main_kernel<<<GRID, NTHREADS, SMEM_TOTAL>>>(G, X, (float*)d_out, m, n);
}